// round 16
// baseline (speedup 1.0000x reference)
#include <cuda_runtime.h>
#include <cuda_bf16.h>
#include <cuda_fp16.h>
#include <cstdint>

#define NPOS 4096
#define NROWS 8192
#define LOG2E 1.4426950408889634f

// ---- scratch (device globals; allocation-free rule) ----
__device__ __align__(16) __nv_bfloat16 g_wth[192 * 256], g_wtl[192 * 256];   // [3*64 n][256 k]
__device__ __align__(16) __half        g_woh[256 * 64];                      // Wo^T fp16 [256 n][64 k]
__device__ __align__(16) __nv_bfloat16 g_kh[NROWS * 64], g_kl[NROWS * 64];   // flash-Q role (bf16, pre-scaled by log2e)
__device__ __align__(16) __nv_bfloat16 g_qh[NROWS * 64], g_ql[NROWS * 64];   // flash-K role (bf16)
__device__ __align__(16) __half        g_vh[NROWS * 64];                     // V (fp16)
__device__ __align__(16) float g_opart[4 * NROWS * 64];  // [split][row][d]
__device__ __align__(16) float g_lpart[4 * NROWS];       // [split][row]
__device__ __align__(16) float g_mpart[4 * NROWS];       // [split][row] (log2 domain)

__device__ __forceinline__ uint32_t smem_to_u32(const void* p) {
    uint32_t a;
    asm("{ .reg .u64 t; cvta.to.shared.u64 t, %1; cvt.u32.u64 %0, t; }" : "=r"(a) : "l"(p));
    return a;
}
__device__ __forceinline__ float ex2(float x) {
    float r;
    asm("ex2.approx.f32 %0, %1;" : "=f"(r) : "f"(x));
    return r;
}
#define CP_ASYNC16(dst, src) asm volatile( \
    "cp.async.cg.shared.global [%0], [%1], 16;" :: "r"(dst), "l"(src) : "memory")
#define CP_COMMIT() asm volatile("cp.async.commit_group;" ::: "memory")
#define CP_WAIT(N)  asm volatile("cp.async.wait_group %0;" :: "n"(N) : "memory")

#define LDSM_X4(r, a) asm volatile( \
    "ldmatrix.sync.aligned.m8n8.x4.shared.b16 {%0,%1,%2,%3}, [%4];" \
    : "=r"((r)[0]), "=r"((r)[1]), "=r"((r)[2]), "=r"((r)[3]) : "r"(a))
#define LDSM_X4T(r, a) asm volatile( \
    "ldmatrix.sync.aligned.m8n8.x4.trans.shared.b16 {%0,%1,%2,%3}, [%4];" \
    : "=r"((r)[0]), "=r"((r)[1]), "=r"((r)[2]), "=r"((r)[3]) : "r"(a))
#define MMA_BF16(c, a, b0, b1) asm volatile( \
    "mma.sync.aligned.m16n8k16.row.col.f32.bf16.bf16.f32 " \
    "{%0,%1,%2,%3}, {%4,%5,%6,%7}, {%8,%9}, {%0,%1,%2,%3};" \
    : "+f"((c)[0]), "+f"((c)[1]), "+f"((c)[2]), "+f"((c)[3]) \
    : "r"((a)[0]), "r"((a)[1]), "r"((a)[2]), "r"((a)[3]), "r"(b0), "r"(b1))
#define MMA_FP16(c, a, b0, b1) asm volatile( \
    "mma.sync.aligned.m16n8k16.row.col.f32.f16.f16.f32 " \
    "{%0,%1,%2,%3}, {%4,%5,%6,%7}, {%8,%9}, {%0,%1,%2,%3};" \
    : "+f"((c)[0]), "+f"((c)[1]), "+f"((c)[2]), "+f"((c)[3]) \
    : "r"((a)[0]), "r"((a)[1]), "r"((a)[2]), "r"((a)[3]), "r"(b0), "r"(b1))

__device__ __forceinline__ void split2pack(float a, float b, uint32_t& hi, uint32_t& lo) {
    __nv_bfloat16 h0 = __float2bfloat16(a), h1 = __float2bfloat16(b);
    __nv_bfloat162 hh = __halves2bfloat162(h0, h1);
    __nv_bfloat162 ll = __floats2bfloat162_rn(a - __bfloat162float(h0),
                                              b - __bfloat162float(h1));
    hi = *(uint32_t*)&hh; lo = *(uint32_t*)&ll;
}
__device__ __forceinline__ uint32_t pack_h2(float a, float b) {
    __half2 h = __floats2half2_rn(a, b);
    return *(uint32_t*)&h;
}

// ============ Kernel 0: transpose+split W (192x256); Wo -> fp16 (256x64) ============
__global__ __launch_bounds__(256) void split_w_kernel(
    const float* __restrict__ Wk, const float* __restrict__ Wq,
    const float* __restrict__ Wv, const float* __restrict__ Wo)
{
    const int bid = blockIdx.x, tid = threadIdx.x;
    if (bid < 192) {
        int j = bid * 256 + tid;
        int m = j >> 14, rem = j & 16383;
        int k = rem >> 6, n = rem & 63;
        const float* W = (m == 0) ? Wk : (m == 1) ? Wq : Wv;
        float v = W[k * 64 + n];
        __nv_bfloat16 h = __float2bfloat16(v);
        int di = (m * 64 + n) * 256 + k;
        g_wth[di] = h;
        g_wtl[di] = __float2bfloat16(v - __bfloat162float(h));
    } else {
        int j = (bid - 192) * 256 + tid;
        int k = j >> 8, n = j & 255;
        g_woh[n * 64 + k] = __float2half_rn(Wo[k * 256 + n]);
    }
}

// ============ Kernel 1: fused x-split + proj mma: [8192,256]@[256,192] ============
#define PSTG 4096
#define PASZ 2560
#define PBSZ 15360
#define PBUF 39936

__device__ __forceinline__ void proj_load(uint32_t sb, int buf, int row0, int k0, int tid,
                                          const float* __restrict__ x) {
    {
        int r = tid >> 3, c4 = tid & 7;
        const char* g = (const char*)(x + (size_t)(row0 + r) * 256 + k0 + c4 * 4);
        CP_ASYNC16(sb + buf * PBUF + r * 128 + c4 * 16, g);
    }
#pragma unroll
    for (int i = 0; i < 6; i++) {
        int j = tid + i * 256;
        int hl = j >= 768; int jj = j - (hl ? 768 : 0);
        int r = jj >> 2, c = jj & 3;
        const __nv_bfloat16* src = (hl ? g_wtl : g_wth) + (size_t)r * 256 + k0 + c * 8;
        CP_ASYNC16(sb + buf * PBUF + PSTG + 2 * PASZ + hl * PBSZ + r * 80 + c * 16,
                   (const char*)src);
    }
}

__global__ __launch_bounds__(256, 2) void proj_mma(const float* __restrict__ x)
{
    extern __shared__ __align__(16) char smem[];
    const uint32_t sb = smem_to_u32(smem);
    const int tid = threadIdx.x;
    const int wid = tid >> 5, lane = tid & 31;
    const int rg = wid & 1, cg = wid >> 1;
    const int row0 = blockIdx.x * 32;

    float c[6][4];
#pragma unroll
    for (int t = 0; t < 6; t++)
#pragma unroll
        for (int j = 0; j < 4; j++) c[t][j] = 0.f;

    proj_load(sb, 0, row0, 0, tid, x);
    CP_COMMIT();

    for (int ch = 0; ch < 8; ch++) {
        __syncthreads();
        if (ch + 1 < 8) {
            proj_load(sb, (ch + 1) & 1, row0, (ch + 1) * 32, tid, x);
            CP_COMMIT(); CP_WAIT(1);
        } else CP_WAIT(0);
        __syncthreads();

        const uint32_t base = sb + (ch & 1) * PBUF;
        {
            int r = tid >> 3, cc = (tid & 7) * 4;
            float4 v = *(const float4*)(smem + (ch & 1) * PBUF + r * 128 + cc * 4);
            uint32_t h0, l0, h1, l1;
            split2pack(v.x, v.y, h0, l0);
            split2pack(v.z, v.w, h1, l1);
            *(uint2*)(smem + (ch & 1) * PBUF + PSTG + r * 80 + cc * 2) = make_uint2(h0, h1);
            *(uint2*)(smem + (ch & 1) * PBUF + PSTG + PASZ + r * 80 + cc * 2) = make_uint2(l0, l1);
        }
        __syncthreads();

        uint32_t ah[2][4], al[2][4];
#pragma unroll
        for (int kt = 0; kt < 2; kt++) {
            uint32_t a = base + PSTG + (16 * rg + (lane & 15)) * 80 + kt * 32 + ((lane >> 4) << 4);
            LDSM_X4(ah[kt], a);
            LDSM_X4(al[kt], a + PASZ);
        }
#pragma unroll
        for (int t = 0; t < 6; t++) {
            int g = cg * 6 + t;
            uint32_t bh[4], bl[4];
            uint32_t ba = base + PSTG + 2 * PASZ + (8 * g + (lane & 7)) * 80 + ((lane >> 3) & 3) * 16;
            LDSM_X4(bh, ba);
            LDSM_X4(bl, ba + PBSZ);
            MMA_BF16(c[t], ah[0], bh[0], bh[1]);
            MMA_BF16(c[t], al[0], bh[0], bh[1]);
            MMA_BF16(c[t], ah[0], bl[0], bl[1]);
            MMA_BF16(c[t], ah[1], bh[2], bh[3]);
            MMA_BF16(c[t], al[1], bh[2], bh[3]);
            MMA_BF16(c[t], ah[1], bl[2], bl[3]);
        }
    }

    uint32_t* hip[3] = { (uint32_t*)g_kh, (uint32_t*)g_qh, (uint32_t*)g_vh };
    uint32_t* lop[2] = { (uint32_t*)g_kl, (uint32_t*)g_ql };
    const int r1 = row0 + 16 * rg + (lane >> 2);
#pragma unroll
    for (int t = 0; t < 6; t++) {
        int g = cg * 6 + t;
        int mat = g >> 3, cu = (g & 7) * 4 + (lane & 3);
        if (mat == 2) {   // V: single fp16
            hip[2][(size_t)r1 * 32 + cu] = pack_h2(c[t][0], c[t][1]);
            hip[2][(size_t)(r1 + 8) * 32 + cu] = pack_h2(c[t][2], c[t][3]);
        } else {
            float f0 = c[t][0], f1 = c[t][1], f2 = c[t][2], f3 = c[t][3];
            if (mat == 0) {   // flash-Q role: pre-scale by log2e (before split: exact)
                f0 *= LOG2E; f1 *= LOG2E; f2 *= LOG2E; f3 *= LOG2E;
            }
            uint32_t h0, l0, h1, l1;
            split2pack(f0, f1, h0, l0);
            split2pack(f2, f3, h1, l1);
            hip[mat][(size_t)r1 * 32 + cu] = h0;
            lop[mat][(size_t)r1 * 32 + cu] = l0;
            hip[mat][(size_t)(r1 + 8) * 32 + cu] = h1;
            lop[mat][(size_t)(r1 + 8) * 32 + cu] = l1;
        }
    }
}

// ========== Kernel 2: flash attention (triple-buffer, 1 sync/tile, ex2) ==========
#define ROWB 144
#define MATB 9216
#define BUFB 27648
#define QOFF 82944          // Q staging after the 3 KV buffers
#define ASMEM (QOFF + 36864)

__device__ __forceinline__ void load_tile(uint32_t sb, uint32_t bufoff, int grow0, int tid) {
    const char* srcs[3] = { (const char*)g_qh, (const char*)g_ql, (const char*)g_vh };
#pragma unroll
    for (int i = 0; i < 6; i++) {
        int idx = tid + i * 256;
        int mat = idx >> 9;
        int r = (idx >> 3) & 63, c8 = idx & 7;
        const char* g = srcs[mat] + ((size_t)(grow0 + r) * 64 + c8 * 8) * 2;
        uint32_t d = sb + bufoff + mat * MATB + r * ROWB + c8 * 16;
        CP_ASYNC16(d, g);
    }
}

__global__ __launch_bounds__(256, 1) void attn_kernel()
{
    extern __shared__ __align__(16) char smem[];
    const uint32_t sb = smem_to_u32(smem);
    const int tid = threadIdx.x;
    const int wid = tid >> 5, lane = tid & 31;
    const int split = blockIdx.x >> 6;
    const int b = (blockIdx.x >> 5) & 1;
    const int n0 = (blockIdx.x & 31) * 128;
    const int kv0 = b * NPOS + split * 1024;
    const int r0 = wid << 4;

    // stage Q (group 1), preload tiles 0,1 (groups 2,3) — overlapped
#pragma unroll
    for (int i = 0; i < 8; i++) {
        int idx = tid + i * 256;
        int m = idx >> 10;
        int r = (idx >> 3) & 127, c8 = idx & 7;
        const __nv_bfloat16* src = m ? g_kl : g_kh;
        const char* g = (const char*)(src + (size_t)(b * NPOS + n0 + r) * 64 + c8 * 8);
        CP_ASYNC16(sb + QOFF + m * 18432 + r * ROWB + c8 * 16, g);
    }
    CP_COMMIT();
    load_tile(sb, 0, kv0, tid);          CP_COMMIT();
    load_tile(sb, BUFB, kv0 + 64, tid);  CP_COMMIT();

    CP_WAIT(2);          // Q done; tiles 0,1 in flight
    __syncthreads();

    uint32_t qh[4][4], ql[4][4];
#pragma unroll
    for (int kt = 0; kt < 4; kt++) {
        uint32_t a = sb + QOFF + (r0 + (lane & 15)) * ROWB + (16 * kt + ((lane >> 4) << 3)) * 2;
        LDSM_X4(qh[kt], a);
        LDSM_X4(ql[kt], a + 18432);
    }

    float o[8][4];
#pragma unroll
    for (int i = 0; i < 8; i++)
#pragma unroll
        for (int j = 0; j < 4; j++) o[i][j] = 0.f;
    float l0 = 0.f, l1 = 0.f, m0 = -1e30f, m1 = -1e30f;

    for (int t = 0; t < 16; t++) {
        if (t + 2 < 16) CP_WAIT(1); else CP_WAIT(0);
        __syncthreads();                 // tile t visible; buffer (t+2)%3 reusable
        if (t + 2 < 16) {
            load_tile(sb, (uint32_t)((t + 2) % 3) * BUFB, kv0 + (t + 2) * 64, tid);
            CP_COMMIT();
        }

        const uint32_t base = sb + (uint32_t)(t % 3) * BUFB;

        // ---- Phase 1: all S for the tile ----
        float cs[4][8];
#pragma unroll
        for (int j = 0; j < 4; j++) {
#pragma unroll
            for (int e = 0; e < 8; e++) cs[j][e] = 0.f;
            uint32_t arow0 = base + (16 * j + (lane & 7)) * ROWB + ((lane >> 3) & 3) * 16;
            uint32_t arow1 = arow0 + 8 * ROWB;
#pragma unroll
            for (int kp = 0; kp < 2; kp++) {
                uint32_t bh[4], bl[4];
                LDSM_X4(bh, arow0 + kp * 64);
                LDSM_X4(bl, arow0 + kp * 64 + MATB);
                MMA_BF16(&cs[j][0], qh[2 * kp], bh[0], bh[1]);
                MMA_BF16(&cs[j][0], ql[2 * kp], bh[0], bh[1]);
                MMA_BF16(&cs[j][0], qh[2 * kp], bl[0], bl[1]);
                MMA_BF16(&cs[j][0], qh[2 * kp + 1], bh[2], bh[3]);
                MMA_BF16(&cs[j][0], ql[2 * kp + 1], bh[2], bh[3]);
                MMA_BF16(&cs[j][0], qh[2 * kp + 1], bl[2], bl[3]);
                LDSM_X4(bh, arow1 + kp * 64);
                LDSM_X4(bl, arow1 + kp * 64 + MATB);
                MMA_BF16(&cs[j][4], qh[2 * kp], bh[0], bh[1]);
                MMA_BF16(&cs[j][4], ql[2 * kp], bh[0], bh[1]);
                MMA_BF16(&cs[j][4], qh[2 * kp], bl[0], bl[1]);
                MMA_BF16(&cs[j][4], qh[2 * kp + 1], bh[2], bh[3]);
                MMA_BF16(&cs[j][4], ql[2 * kp + 1], bh[2], bh[3]);
                MMA_BF16(&cs[j][4], qh[2 * kp + 1], bl[2], bl[3]);
            }
        }

        // ---- Phase 2: per-tile max (log2 domain), conditional rescale ----
        float jm0 = -1e30f, jm1 = -1e30f;
#pragma unroll
        for (int j = 0; j < 4; j++) {
            jm0 = fmaxf(jm0, fmaxf(fmaxf(cs[j][0], cs[j][1]), fmaxf(cs[j][4], cs[j][5])));
            jm1 = fmaxf(jm1, fmaxf(fmaxf(cs[j][2], cs[j][3]), fmaxf(cs[j][6], cs[j][7])));
        }
        jm0 = fmaxf(jm0, __shfl_xor_sync(0xffffffffu, jm0, 1));
        jm0 = fmaxf(jm0, __shfl_xor_sync(0xffffffffu, jm0, 2));
        jm1 = fmaxf(jm1, __shfl_xor_sync(0xffffffffu, jm1, 1));
        jm1 = fmaxf(jm1, __shfl_xor_sync(0xffffffffu, jm1, 2));
        float m0o = m0, m1o = m1;
        m0 = fmaxf(m0, jm0); m1 = fmaxf(m1, jm1);
        bool nochange = (m0 == m0o) && (m1 == m1o);
        if (!__all_sync(0xffffffffu, nochange)) {
            float s0 = ex2(m0o - m0), s1 = ex2(m1o - m1);   // exact 1.0 when unchanged
            l0 *= s0; l1 *= s1;
#pragma unroll
            for (int dt = 0; dt < 8; dt++) {
                o[dt][0] *= s0; o[dt][1] *= s0;
                o[dt][2] *= s1; o[dt][3] *= s1;
            }
        }

        // ---- Phase 3: ex2 + PV per j ----
#pragma unroll
        for (int j = 0; j < 4; j++) {
            float p00 = ex2(cs[j][0] - m0), p01 = ex2(cs[j][1] - m0);
            float p02 = ex2(cs[j][2] - m1), p03 = ex2(cs[j][3] - m1);
            float p10 = ex2(cs[j][4] - m0), p11 = ex2(cs[j][5] - m0);
            float p12 = ex2(cs[j][6] - m1), p13 = ex2(cs[j][7] - m1);
            l0 += (p00 + p01) + (p10 + p11);
            l1 += (p02 + p03) + (p12 + p13);
            uint32_t ph[4];
            ph[0] = pack_h2(p00, p01);
            ph[1] = pack_h2(p02, p03);
            ph[2] = pack_h2(p10, p11);
            ph[3] = pack_h2(p12, p13);
#pragma unroll
            for (int dp = 0; dp < 4; dp++) {
                uint32_t av = base + 2 * MATB + (16 * j + (lane & 15)) * ROWB
                              + dp * 32 + ((lane >> 4) & 1) * 16;
                uint32_t vh[4];
                LDSM_X4T(vh, av);
                MMA_FP16(o[2 * dp], ph, vh[0], vh[1]);
                MMA_FP16(o[2 * dp + 1], ph, vh[2], vh[3]);
            }
        }
    }

    l0 += __shfl_xor_sync(0xffffffffu, l0, 1);
    l0 += __shfl_xor_sync(0xffffffffu, l0, 2);
    l1 += __shfl_xor_sync(0xffffffffu, l1, 1);
    l1 += __shfl_xor_sync(0xffffffffu, l1, 2);

    const int rg = b * NPOS + n0 + r0 + (lane >> 2);
    float* dst = g_opart + (size_t)split * NROWS * 64;
#pragma unroll
    for (int dt = 0; dt < 8; dt++) {
        ((float2*)(dst + (size_t)rg * 64 + dt * 8))[lane & 3] =
            make_float2(o[dt][0], o[dt][1]);
        ((float2*)(dst + (size_t)(rg + 8) * 64 + dt * 8))[lane & 3] =
            make_float2(o[dt][2], o[dt][3]);
    }
    if ((lane & 3) == 0) {
        g_lpart[split * NROWS + rg] = l0;
        g_lpart[split * NROWS + rg + 8] = l1;
        g_mpart[split * NROWS + rg] = m0;
        g_mpart[split * NROWS + rg + 8] = m1;
    }
}

// ====== Kernel 3: merge 4 splits (log2-domain) + outproj fp16 + BN ======
#define OAH 4608
#define OBH 36864

__global__ __launch_bounds__(256, 2) void outproj_mma(
    const float* __restrict__ gamma, const float* __restrict__ beta,
    float* __restrict__ out)
{
    extern __shared__ __align__(16) char smem[];
    const uint32_t sb = smem_to_u32(smem);
    const int tid = threadIdx.x;
    const int wid = tid >> 5, lane = tid & 31;
    const int rg = wid & 1, cg = wid >> 1;
    const int row0 = blockIdx.x * 32;

#pragma unroll
    for (int i = 0; i < 8; i++) {
        int idx = tid + i * 256;
        int r = idx >> 3, c = idx & 7;
        CP_ASYNC16(sb + OAH + r * ROWB + c * 16, (const char*)(g_woh + r * 64 + c * 8));
    }
    CP_COMMIT();

    {
        int r = tid >> 3, cq = tid & 7;
        int rgr = row0 + r;
        float ms[4], w[4];
        float M = -1e30f;
#pragma unroll
        for (int s = 0; s < 4; s++) {
            ms[s] = g_mpart[s * NROWS + rgr];
            M = fmaxf(M, ms[s]);
        }
        float denom = 0.f;
#pragma unroll
        for (int s = 0; s < 4; s++) {
            w[s] = ex2(ms[s] - M);
            denom += w[s] * g_lpart[s * NROWS + rgr];
        }
        float inv = 1.f / denom;
        uint32_t hpk[4];
#pragma unroll
        for (int e = 0; e < 2; e++) {
            int c4 = cq * 2 + e;
            float4 u = make_float4(0.f, 0.f, 0.f, 0.f);
#pragma unroll
            for (int s = 0; s < 4; s++) {
                float4 p = ((const float4*)(g_opart + (size_t)s * NROWS * 64
                                            + (size_t)rgr * 64))[c4];
                u.x += w[s] * p.x; u.y += w[s] * p.y;
                u.z += w[s] * p.z; u.w += w[s] * p.w;
            }
            hpk[2 * e]     = pack_h2(u.x * inv, u.y * inv);
            hpk[2 * e + 1] = pack_h2(u.z * inv, u.w * inv);
        }
        *(uint4*)(smem + r * ROWB + cq * 16) =
            make_uint4(hpk[0], hpk[1], hpk[2], hpk[3]);
    }
    CP_WAIT(0);
    __syncthreads();

    uint32_t ah[4][4];
#pragma unroll
    for (int kt = 0; kt < 4; kt++) {
        uint32_t a = sb + (16 * rg + (lane & 15)) * ROWB + kt * 32 + ((lane >> 4) << 4);
        LDSM_X4(ah[kt], a);
    }

    float acc[8][4];
#pragma unroll
    for (int t = 0; t < 8; t++)
#pragma unroll
        for (int j = 0; j < 4; j++) acc[t][j] = 0.f;

#pragma unroll
    for (int t = 0; t < 8; t++) {
        int nrow0 = cg * 64 + t * 8;
#pragma unroll
        for (int kp = 0; kp < 2; kp++) {
            uint32_t bh[4];
            uint32_t ba = sb + OAH + (nrow0 + (lane & 7)) * ROWB
                          + kp * 64 + ((lane >> 3) & 3) * 16;
            LDSM_X4(bh, ba);
            MMA_FP16(acc[t], ah[2 * kp], bh[0], bh[1]);
            MMA_FP16(acc[t], ah[2 * kp + 1], bh[2], bh[3]);
        }
    }

    const float sc = rsqrtf(1.0f + 1e-3f);
    const int r1 = row0 + 16 * rg + (lane >> 2);
#pragma unroll
    for (int t = 0; t < 8; t++) {
        int col = cg * 64 + t * 8 + (lane & 3) * 2;
        float g0 = __ldg(gamma + col) * sc, g1 = __ldg(gamma + col + 1) * sc;
        float b0 = __ldg(beta + col), b1 = __ldg(beta + col + 1);
        *(float2*)(out + (size_t)r1 * 256 + col) =
            make_float2(fmaf(acc[t][0], g0, b0), fmaf(acc[t][1], g1, b1));
        *(float2*)(out + (size_t)(r1 + 8) * 256 + col) =
            make_float2(fmaf(acc[t][2], g0, b0), fmaf(acc[t][3], g1, b1));
    }
}

extern "C" void kernel_launch(void* const* d_in, const int* in_sizes, int n_in,
                              void* d_out, int out_size) {
    const float* x     = (const float*)d_in[0];
    const float* Wk    = (const float*)d_in[1];
    const float* Wq    = (const float*)d_in[2];
    const float* Wv    = (const float*)d_in[3];
    const float* Wo    = (const float*)d_in[4];
    const float* gamma = (const float*)d_in[5];
    const float* beta  = (const float*)d_in[6];
    float* out = (float*)d_out;

    cudaFuncSetAttribute(proj_mma, cudaFuncAttributeMaxDynamicSharedMemorySize, 2 * PBUF);
    cudaFuncSetAttribute(attn_kernel, cudaFuncAttributeMaxDynamicSharedMemorySize, ASMEM);
    cudaFuncSetAttribute(outproj_mma, cudaFuncAttributeMaxDynamicSharedMemorySize,
                         OAH + OBH);

    split_w_kernel<<<256, 256>>>(Wk, Wq, Wv, Wo);
    proj_mma<<<256, 256, 2 * PBUF>>>(x);
    attn_kernel<<<256, 256, ASMEM>>>();
    outproj_mma<<<256, 256, OAH + OBH>>>(gamma, beta, out);
}

// round 17
// speedup vs baseline: 1.0233x; 1.0233x over previous
#include <cuda_runtime.h>
#include <cuda_bf16.h>
#include <cuda_fp16.h>
#include <cstdint>

#define NPOS 4096
#define NROWS 8192

// ---- scratch (device globals; allocation-free rule) ----
__device__ __align__(16) __nv_bfloat16 g_wth[192 * 256], g_wtl[192 * 256];   // [3*64 n][256 k]
__device__ __align__(16) __half        g_woh[256 * 64];                      // Wo^T fp16 [256 n][64 k]
__device__ __align__(16) __half g_kh[NROWS * 64], g_kl[NROWS * 64];          // flash-Q role (fp16 split)
__device__ __align__(16) __half g_qh[NROWS * 64], g_ql[NROWS * 64];          // flash-K role (fp16 split)
__device__ __align__(16) __half g_vh[NROWS * 64];                            // V (fp16)
__device__ __align__(16) float g_opart[4 * NROWS * 64];  // [split][row][d]
__device__ __align__(16) float g_lpart[4 * NROWS];       // [split][row]
__device__ __align__(16) float g_mpart[4 * NROWS];       // [split][row]

__device__ __forceinline__ uint32_t smem_to_u32(const void* p) {
    uint32_t a;
    asm("{ .reg .u64 t; cvta.to.shared.u64 t, %1; cvt.u32.u64 %0, t; }" : "=r"(a) : "l"(p));
    return a;
}
#define CP_ASYNC16(dst, src) asm volatile( \
    "cp.async.cg.shared.global [%0], [%1], 16;" :: "r"(dst), "l"(src) : "memory")
#define CP_COMMIT() asm volatile("cp.async.commit_group;" ::: "memory")
#define CP_WAIT(N)  asm volatile("cp.async.wait_group %0;" :: "n"(N) : "memory")

#define LDSM_X4(r, a) asm volatile( \
    "ldmatrix.sync.aligned.m8n8.x4.shared.b16 {%0,%1,%2,%3}, [%4];" \
    : "=r"((r)[0]), "=r"((r)[1]), "=r"((r)[2]), "=r"((r)[3]) : "r"(a))
#define LDSM_X4T(r, a) asm volatile( \
    "ldmatrix.sync.aligned.m8n8.x4.trans.shared.b16 {%0,%1,%2,%3}, [%4];" \
    : "=r"((r)[0]), "=r"((r)[1]), "=r"((r)[2]), "=r"((r)[3]) : "r"(a))
#define MMA_BF16(c, a, b0, b1) asm volatile( \
    "mma.sync.aligned.m16n8k16.row.col.f32.bf16.bf16.f32 " \
    "{%0,%1,%2,%3}, {%4,%5,%6,%7}, {%8,%9}, {%0,%1,%2,%3};" \
    : "+f"((c)[0]), "+f"((c)[1]), "+f"((c)[2]), "+f"((c)[3]) \
    : "r"((a)[0]), "r"((a)[1]), "r"((a)[2]), "r"((a)[3]), "r"(b0), "r"(b1))
#define MMA_FP16(c, a, b0, b1) asm volatile( \
    "mma.sync.aligned.m16n8k16.row.col.f32.f16.f16.f32 " \
    "{%0,%1,%2,%3}, {%4,%5,%6,%7}, {%8,%9}, {%0,%1,%2,%3};" \
    : "+f"((c)[0]), "+f"((c)[1]), "+f"((c)[2]), "+f"((c)[3]) \
    : "r"((a)[0]), "r"((a)[1]), "r"((a)[2]), "r"((a)[3]), "r"(b0), "r"(b1))

__device__ __forceinline__ void split2pack(float a, float b, uint32_t& hi, uint32_t& lo) {
    __nv_bfloat16 h0 = __float2bfloat16(a), h1 = __float2bfloat16(b);
    __nv_bfloat162 hh = __halves2bfloat162(h0, h1);
    __nv_bfloat162 ll = __floats2bfloat162_rn(a - __bfloat162float(h0),
                                              b - __bfloat162float(h1));
    hi = *(uint32_t*)&hh; lo = *(uint32_t*)&ll;
}
__device__ __forceinline__ void split2pack_h(float a, float b, uint32_t& hi, uint32_t& lo) {
    __half h0 = __float2half_rn(a), h1 = __float2half_rn(b);
    __half2 hh = __halves2half2(h0, h1);
    __half2 ll = __floats2half2_rn(a - __half2float(h0), b - __half2float(h1));
    hi = *(uint32_t*)&hh; lo = *(uint32_t*)&ll;
}
__device__ __forceinline__ uint32_t pack_h2(float a, float b) {
    __half2 h = __floats2half2_rn(a, b);
    return *(uint32_t*)&h;
}

// ============ Kernel 0: transpose+split W (192x256); Wo -> fp16 (256x64) ============
__global__ __launch_bounds__(256) void split_w_kernel(
    const float* __restrict__ Wk, const float* __restrict__ Wq,
    const float* __restrict__ Wv, const float* __restrict__ Wo)
{
    const int bid = blockIdx.x, tid = threadIdx.x;
    if (bid < 192) {
        int j = bid * 256 + tid;
        int m = j >> 14, rem = j & 16383;
        int k = rem >> 6, n = rem & 63;
        const float* W = (m == 0) ? Wk : (m == 1) ? Wq : Wv;
        float v = W[k * 64 + n];
        __nv_bfloat16 h = __float2bfloat16(v);
        int di = (m * 64 + n) * 256 + k;
        g_wth[di] = h;
        g_wtl[di] = __float2bfloat16(v - __bfloat162float(h));
    } else {
        int j = (bid - 192) * 256 + tid;
        int k = j >> 8, n = j & 255;
        g_woh[n * 64 + k] = __float2half_rn(Wo[k * 256 + n]);
    }
}

// ============ Kernel 1: fused x-split + proj mma: [8192,256]@[256,192] ============
#define PSTG 4096
#define PASZ 2560
#define PBSZ 15360
#define PBUF 39936

__device__ __forceinline__ void proj_load(uint32_t sb, int buf, int row0, int k0, int tid,
                                          const float* __restrict__ x) {
    {
        int r = tid >> 3, c4 = tid & 7;
        const char* g = (const char*)(x + (size_t)(row0 + r) * 256 + k0 + c4 * 4);
        CP_ASYNC16(sb + buf * PBUF + r * 128 + c4 * 16, g);
    }
#pragma unroll
    for (int i = 0; i < 6; i++) {
        int j = tid + i * 256;
        int hl = j >= 768; int jj = j - (hl ? 768 : 0);
        int r = jj >> 2, c = jj & 3;
        const __nv_bfloat16* src = (hl ? g_wtl : g_wth) + (size_t)r * 256 + k0 + c * 8;
        CP_ASYNC16(sb + buf * PBUF + PSTG + 2 * PASZ + hl * PBSZ + r * 80 + c * 16,
                   (const char*)src);
    }
}

__global__ __launch_bounds__(256, 2) void proj_mma(const float* __restrict__ x)
{
    extern __shared__ __align__(16) char smem[];
    const uint32_t sb = smem_to_u32(smem);
    const int tid = threadIdx.x;
    const int wid = tid >> 5, lane = tid & 31;
    const int rg = wid & 1, cg = wid >> 1;
    const int row0 = blockIdx.x * 32;

    float c[6][4];
#pragma unroll
    for (int t = 0; t < 6; t++)
#pragma unroll
        for (int j = 0; j < 4; j++) c[t][j] = 0.f;

    proj_load(sb, 0, row0, 0, tid, x);
    CP_COMMIT();

    for (int ch = 0; ch < 8; ch++) {
        __syncthreads();
        if (ch + 1 < 8) {
            proj_load(sb, (ch + 1) & 1, row0, (ch + 1) * 32, tid, x);
            CP_COMMIT(); CP_WAIT(1);
        } else CP_WAIT(0);
        __syncthreads();

        const uint32_t base = sb + (ch & 1) * PBUF;
        {
            int r = tid >> 3, cc = (tid & 7) * 4;
            float4 v = *(const float4*)(smem + (ch & 1) * PBUF + r * 128 + cc * 4);
            uint32_t h0, l0, h1, l1;
            split2pack(v.x, v.y, h0, l0);
            split2pack(v.z, v.w, h1, l1);
            *(uint2*)(smem + (ch & 1) * PBUF + PSTG + r * 80 + cc * 2) = make_uint2(h0, h1);
            *(uint2*)(smem + (ch & 1) * PBUF + PSTG + PASZ + r * 80 + cc * 2) = make_uint2(l0, l1);
        }
        __syncthreads();

        uint32_t ah[2][4], al[2][4];
#pragma unroll
        for (int kt = 0; kt < 2; kt++) {
            uint32_t a = base + PSTG + (16 * rg + (lane & 15)) * 80 + kt * 32 + ((lane >> 4) << 4);
            LDSM_X4(ah[kt], a);
            LDSM_X4(al[kt], a + PASZ);
        }
#pragma unroll
        for (int t = 0; t < 6; t++) {
            int g = cg * 6 + t;
            uint32_t bh[4], bl[4];
            uint32_t ba = base + PSTG + 2 * PASZ + (8 * g + (lane & 7)) * 80 + ((lane >> 3) & 3) * 16;
            LDSM_X4(bh, ba);
            LDSM_X4(bl, ba + PBSZ);
            MMA_BF16(c[t], ah[0], bh[0], bh[1]);
            MMA_BF16(c[t], al[0], bh[0], bh[1]);
            MMA_BF16(c[t], ah[0], bl[0], bl[1]);
            MMA_BF16(c[t], ah[1], bh[2], bh[3]);
            MMA_BF16(c[t], al[1], bh[2], bh[3]);
            MMA_BF16(c[t], ah[1], bl[2], bl[3]);
        }
    }

    uint32_t* hip[3] = { (uint32_t*)g_kh, (uint32_t*)g_qh, (uint32_t*)g_vh };
    uint32_t* lop[2] = { (uint32_t*)g_kl, (uint32_t*)g_ql };
    const int r1 = row0 + 16 * rg + (lane >> 2);
#pragma unroll
    for (int t = 0; t < 6; t++) {
        int g = cg * 6 + t;
        int mat = g >> 3, cu = (g & 7) * 4 + (lane & 3);
        if (mat == 2) {   // V: single fp16
            hip[2][(size_t)r1 * 32 + cu] = pack_h2(c[t][0], c[t][1]);
            hip[2][(size_t)(r1 + 8) * 32 + cu] = pack_h2(c[t][2], c[t][3]);
        } else {          // k/q: fp16 hi/lo splits
            uint32_t h0, l0, h1, l1;
            split2pack_h(c[t][0], c[t][1], h0, l0);
            split2pack_h(c[t][2], c[t][3], h1, l1);
            hip[mat][(size_t)r1 * 32 + cu] = h0;
            lop[mat][(size_t)r1 * 32 + cu] = l0;
            hip[mat][(size_t)(r1 + 8) * 32 + cu] = h1;
            lop[mat][(size_t)(r1 + 8) * 32 + cu] = l1;
        }
    }
}

// ========== Kernel 2: mma.sync flash attention (fp16 S, per-tile hoisted max) ==========
#define ROWB 144
#define MATB 9216
#define BUFB 27648

__device__ __forceinline__ void load_tile(uint32_t sb, int buf, int grow0, int tid) {
    const char* srcs[3] = { (const char*)g_qh, (const char*)g_ql, (const char*)g_vh };
#pragma unroll
    for (int i = 0; i < 6; i++) {
        int idx = tid + i * 256;
        int mat = idx >> 9;
        int r = (idx >> 3) & 63, c8 = idx & 7;
        const char* g = srcs[mat] + ((size_t)(grow0 + r) * 64 + c8 * 8) * 2;
        uint32_t d = sb + buf * BUFB + mat * MATB + r * ROWB + c8 * 16;
        CP_ASYNC16(d, g);
    }
}

__global__ __launch_bounds__(256, 1) void attn_kernel()
{
    extern __shared__ __align__(16) char smem[];
    const uint32_t sb = smem_to_u32(smem);
    const int tid = threadIdx.x;
    const int wid = tid >> 5, lane = tid & 31;
    const int split = blockIdx.x >> 6;
    const int b = (blockIdx.x >> 5) & 1;
    const int n0 = (blockIdx.x & 31) * 128;
    const int kv0 = b * NPOS + split * 1024;
    const int r0 = wid << 4;

#pragma unroll
    for (int i = 0; i < 8; i++) {
        int idx = tid + i * 256;
        int m = idx >> 10;
        int r = (idx >> 3) & 127, c8 = idx & 7;
        const __half* src = m ? g_kl : g_kh;
        const char* g = (const char*)(src + (size_t)(b * NPOS + n0 + r) * 64 + c8 * 8);
        CP_ASYNC16(sb + m * 18432 + r * ROWB + c8 * 16, g);
    }
    CP_COMMIT(); CP_WAIT(0);
    __syncthreads();

    uint32_t qh[4][4], ql[4][4];
#pragma unroll
    for (int kt = 0; kt < 4; kt++) {
        uint32_t a = sb + (r0 + (lane & 15)) * ROWB + (16 * kt + ((lane >> 4) << 3)) * 2;
        LDSM_X4(qh[kt], a);
        LDSM_X4(ql[kt], a + 18432);
    }
    __syncthreads();

    float o[8][4];
#pragma unroll
    for (int i = 0; i < 8; i++)
#pragma unroll
        for (int j = 0; j < 4; j++) o[i][j] = 0.f;
    float l0 = 0.f, l1 = 0.f, m0 = -1e30f, m1 = -1e30f;

    load_tile(sb, 0, kv0, tid);
    CP_COMMIT();

    for (int t = 0; t < 16; t++) {
        __syncthreads();
        if (t + 1 < 16) {
            load_tile(sb, (t + 1) & 1, kv0 + (t + 1) * 64, tid);
            CP_COMMIT(); CP_WAIT(1);
        } else CP_WAIT(0);
        __syncthreads();

        const uint32_t base = sb + (t & 1) * BUFB;

        float cs[4][8];
#pragma unroll
        for (int j = 0; j < 4; j++) {
#pragma unroll
            for (int e = 0; e < 8; e++) cs[j][e] = 0.f;
            uint32_t arow0 = base + (16 * j + (lane & 7)) * ROWB + ((lane >> 3) & 3) * 16;
            uint32_t arow1 = arow0 + 8 * ROWB;
#pragma unroll
            for (int kp = 0; kp < 2; kp++) {
                uint32_t bh[4], bl[4];
                LDSM_X4(bh, arow0 + kp * 64);
                LDSM_X4(bl, arow0 + kp * 64 + MATB);
                MMA_FP16(&cs[j][0], qh[2 * kp], bh[0], bh[1]);
                MMA_FP16(&cs[j][0], ql[2 * kp], bh[0], bh[1]);
                MMA_FP16(&cs[j][0], qh[2 * kp], bl[0], bl[1]);
                MMA_FP16(&cs[j][0], qh[2 * kp + 1], bh[2], bh[3]);
                MMA_FP16(&cs[j][0], ql[2 * kp + 1], bh[2], bh[3]);
                MMA_FP16(&cs[j][0], qh[2 * kp + 1], bl[2], bl[3]);
                LDSM_X4(bh, arow1 + kp * 64);
                LDSM_X4(bl, arow1 + kp * 64 + MATB);
                MMA_FP16(&cs[j][4], qh[2 * kp], bh[0], bh[1]);
                MMA_FP16(&cs[j][4], ql[2 * kp], bh[0], bh[1]);
                MMA_FP16(&cs[j][4], qh[2 * kp], bl[0], bl[1]);
                MMA_FP16(&cs[j][4], qh[2 * kp + 1], bh[2], bh[3]);
                MMA_FP16(&cs[j][4], ql[2 * kp + 1], bh[2], bh[3]);
                MMA_FP16(&cs[j][4], qh[2 * kp + 1], bl[2], bl[3]);
            }
        }

        float jm0 = -1e30f, jm1 = -1e30f;
#pragma unroll
        for (int j = 0; j < 4; j++) {
            jm0 = fmaxf(jm0, fmaxf(fmaxf(cs[j][0], cs[j][1]), fmaxf(cs[j][4], cs[j][5])));
            jm1 = fmaxf(jm1, fmaxf(fmaxf(cs[j][2], cs[j][3]), fmaxf(cs[j][6], cs[j][7])));
        }
        jm0 = fmaxf(jm0, __shfl_xor_sync(0xffffffffu, jm0, 1));
        jm0 = fmaxf(jm0, __shfl_xor_sync(0xffffffffu, jm0, 2));
        jm1 = fmaxf(jm1, __shfl_xor_sync(0xffffffffu, jm1, 1));
        jm1 = fmaxf(jm1, __shfl_xor_sync(0xffffffffu, jm1, 2));
        float m0n = fmaxf(m0, jm0), m1n = fmaxf(m1, jm1);
        float s0 = __expf(m0 - m0n), s1 = __expf(m1 - m1n);
        m0 = m0n; m1 = m1n;
        l0 *= s0; l1 *= s1;
#pragma unroll
        for (int dt = 0; dt < 8; dt++) {
            o[dt][0] *= s0; o[dt][1] *= s0;
            o[dt][2] *= s1; o[dt][3] *= s1;
        }

#pragma unroll
        for (int j = 0; j < 4; j++) {
            float p00 = __expf(cs[j][0] - m0), p01 = __expf(cs[j][1] - m0);
            float p02 = __expf(cs[j][2] - m1), p03 = __expf(cs[j][3] - m1);
            float p10 = __expf(cs[j][4] - m0), p11 = __expf(cs[j][5] - m0);
            float p12 = __expf(cs[j][6] - m1), p13 = __expf(cs[j][7] - m1);
            l0 += (p00 + p01) + (p10 + p11);
            l1 += (p02 + p03) + (p12 + p13);
            uint32_t ph[4];
            ph[0] = pack_h2(p00, p01);
            ph[1] = pack_h2(p02, p03);
            ph[2] = pack_h2(p10, p11);
            ph[3] = pack_h2(p12, p13);
#pragma unroll
            for (int dp = 0; dp < 4; dp++) {
                uint32_t av = base + 2 * MATB + (16 * j + (lane & 15)) * ROWB
                              + dp * 32 + ((lane >> 4) & 1) * 16;
                uint32_t vh[4];
                LDSM_X4T(vh, av);
                MMA_FP16(o[2 * dp], ph, vh[0], vh[1]);
                MMA_FP16(o[2 * dp + 1], ph, vh[2], vh[3]);
            }
        }
    }

    l0 += __shfl_xor_sync(0xffffffffu, l0, 1);
    l0 += __shfl_xor_sync(0xffffffffu, l0, 2);
    l1 += __shfl_xor_sync(0xffffffffu, l1, 1);
    l1 += __shfl_xor_sync(0xffffffffu, l1, 2);

    const int rg = b * NPOS + n0 + r0 + (lane >> 2);
    float* dst = g_opart + (size_t)split * NROWS * 64;
#pragma unroll
    for (int dt = 0; dt < 8; dt++) {
        ((float2*)(dst + (size_t)rg * 64 + dt * 8))[lane & 3] =
            make_float2(o[dt][0], o[dt][1]);
        ((float2*)(dst + (size_t)(rg + 8) * 64 + dt * 8))[lane & 3] =
            make_float2(o[dt][2], o[dt][3]);
    }
    if ((lane & 3) == 0) {
        g_lpart[split * NROWS + rg] = l0;
        g_lpart[split * NROWS + rg + 8] = l1;
        g_mpart[split * NROWS + rg] = m0;
        g_mpart[split * NROWS + rg + 8] = m1;
    }
}

// ====== Kernel 3: merge 4 splits + outproj (single-term fp16) + BN ======
#define OAH 4608
#define OBH 36864

__global__ __launch_bounds__(256, 2) void outproj_mma(
    const float* __restrict__ gamma, const float* __restrict__ beta,
    float* __restrict__ out)
{
    extern __shared__ __align__(16) char smem[];
    const uint32_t sb = smem_to_u32(smem);
    const int tid = threadIdx.x;
    const int wid = tid >> 5, lane = tid & 31;
    const int rg = wid & 1, cg = wid >> 1;
    const int row0 = blockIdx.x * 32;

#pragma unroll
    for (int i = 0; i < 8; i++) {
        int idx = tid + i * 256;
        int r = idx >> 3, c = idx & 7;
        CP_ASYNC16(sb + OAH + r * ROWB + c * 16, (const char*)(g_woh + r * 64 + c * 8));
    }
    CP_COMMIT();

    {
        int r = tid >> 3, cq = tid & 7;
        int rgr = row0 + r;
        float ms[4], w[4];
        float M = -1e30f;
#pragma unroll
        for (int s = 0; s < 4; s++) {
            ms[s] = g_mpart[s * NROWS + rgr];
            M = fmaxf(M, ms[s]);
        }
        float denom = 0.f;
#pragma unroll
        for (int s = 0; s < 4; s++) {
            w[s] = __expf(ms[s] - M);
            denom += w[s] * g_lpart[s * NROWS + rgr];
        }
        float inv = 1.f / denom;
        uint32_t hpk[4];
#pragma unroll
        for (int e = 0; e < 2; e++) {
            int c4 = cq * 2 + e;
            float4 u = make_float4(0.f, 0.f, 0.f, 0.f);
#pragma unroll
            for (int s = 0; s < 4; s++) {
                float4 p = ((const float4*)(g_opart + (size_t)s * NROWS * 64
                                            + (size_t)rgr * 64))[c4];
                u.x += w[s] * p.x; u.y += w[s] * p.y;
                u.z += w[s] * p.z; u.w += w[s] * p.w;
            }
            hpk[2 * e]     = pack_h2(u.x * inv, u.y * inv);
            hpk[2 * e + 1] = pack_h2(u.z * inv, u.w * inv);
        }
        *(uint4*)(smem + r * ROWB + cq * 16) =
            make_uint4(hpk[0], hpk[1], hpk[2], hpk[3]);
    }
    CP_WAIT(0);
    __syncthreads();

    uint32_t ah[4][4];
#pragma unroll
    for (int kt = 0; kt < 4; kt++) {
        uint32_t a = sb + (16 * rg + (lane & 15)) * ROWB + kt * 32 + ((lane >> 4) << 4);
        LDSM_X4(ah[kt], a);
    }

    float acc[8][4];
#pragma unroll
    for (int t = 0; t < 8; t++)
#pragma unroll
        for (int j = 0; j < 4; j++) acc[t][j] = 0.f;

#pragma unroll
    for (int t = 0; t < 8; t++) {
        int nrow0 = cg * 64 + t * 8;
#pragma unroll
        for (int kp = 0; kp < 2; kp++) {
            uint32_t bh[4];
            uint32_t ba = sb + OAH + (nrow0 + (lane & 7)) * ROWB
                          + kp * 64 + ((lane >> 3) & 3) * 16;
            LDSM_X4(bh, ba);
            MMA_FP16(acc[t], ah[2 * kp], bh[0], bh[1]);
            MMA_FP16(acc[t], ah[2 * kp + 1], bh[2], bh[3]);
        }
    }

    const float sc = rsqrtf(1.0f + 1e-3f);
    const int r1 = row0 + 16 * rg + (lane >> 2);
#pragma unroll
    for (int t = 0; t < 8; t++) {
        int col = cg * 64 + t * 8 + (lane & 3) * 2;
        float g0 = __ldg(gamma + col) * sc, g1 = __ldg(gamma + col + 1) * sc;
        float b0 = __ldg(beta + col), b1 = __ldg(beta + col + 1);
        *(float2*)(out + (size_t)r1 * 256 + col) =
            make_float2(fmaf(acc[t][0], g0, b0), fmaf(acc[t][1], g1, b1));
        *(float2*)(out + (size_t)(r1 + 8) * 256 + col) =
            make_float2(fmaf(acc[t][2], g0, b0), fmaf(acc[t][3], g1, b1));
    }
}

extern "C" void kernel_launch(void* const* d_in, const int* in_sizes, int n_in,
                              void* d_out, int out_size) {
    const float* x     = (const float*)d_in[0];
    const float* Wk    = (const float*)d_in[1];
    const float* Wq    = (const float*)d_in[2];
    const float* Wv    = (const float*)d_in[3];
    const float* Wo    = (const float*)d_in[4];
    const float* gamma = (const float*)d_in[5];
    const float* beta  = (const float*)d_in[6];
    float* out = (float*)d_out;

    cudaFuncSetAttribute(proj_mma, cudaFuncAttributeMaxDynamicSharedMemorySize, 2 * PBUF);
    cudaFuncSetAttribute(attn_kernel, cudaFuncAttributeMaxDynamicSharedMemorySize, 2 * BUFB);
    cudaFuncSetAttribute(outproj_mma, cudaFuncAttributeMaxDynamicSharedMemorySize,
                         OAH + OBH);

    split_w_kernel<<<256, 256>>>(Wk, Wq, Wv, Wo);
    proj_mma<<<256, 256, 2 * PBUF>>>(x);
    attn_kernel<<<256, 256, 2 * BUFB>>>();
    outproj_mma<<<256, 256, OAH + OBH>>>(gamma, beta, out);
}